// round 3
// baseline (speedup 1.0000x reference)
#include <cuda_runtime.h>
#include <math.h>

// ---------------- problem constants ----------------
#define BB   2
#define NN   2048
#define MM   64
#define CC   128
#define C2   256
#define BNR  4096                 // BB*NN rows
#define PCNT 262144               // BNR*MM pairwise positions
#define OUTC 64
#define EPS  1e-5f
#define SLOPE 0.2f

// ---------------- device scratch (static, allowed) ----------------
__device__ float g_P  [BNR*CC];          // point @ Wp^T
__device__ float g_Cc [BB*MM*CC];        // center @ Wc^T
__device__ float g_W2t[CC*C2];           // W2 transposed [c][o]
__device__ float g_W3t[C2*C2];           // W3 transposed [c][o]
__device__ float g_z2 [(size_t)PCNT*C2]; // raw layer-2 pre-activations (256MB)
__device__ float g_zmax[BNR*C2];
__device__ float g_zmin[BNR*C2];
__device__ float g_z4 [BNR*128];
__device__ float g_z5 [BNR*OUTC];

__device__ float g_Sp[BB*CC], g_Sp2[BB*CC], g_Sc[BB*CC], g_Sc2[BB*CC];
__device__ float g_a1[CC], g_d1[CC];
__device__ float g_s2[C2], g_q2[C2], g_a2[C2], g_d2[C2];
__device__ float g_s3[C2], g_q3[C2], g_a3[C2], g_d3[C2];
__device__ float g_s4[128], g_q4[128], g_a4[128], g_d4[128];
__device__ float g_s5[OUTC], g_q5[OUTC], g_a5[OUTC], g_d5[OUTC];

// ---------------- K0: zero accumulators + transpose weights ----------------
__global__ void rn_prep(const float* __restrict__ W2, const float* __restrict__ W3) {
    int tid = blockIdx.x * blockDim.x + threadIdx.x;   // grid 256x256 -> 65536
    if (tid < C2) { g_s2[tid] = 0.f; g_q2[tid] = 0.f; g_s3[tid] = 0.f; g_q3[tid] = 0.f; }
    if (tid < 128) { g_s4[tid] = 0.f; g_q4[tid] = 0.f; }
    if (tid < OUTC) { g_s5[tid] = 0.f; g_q5[tid] = 0.f; }
    if (tid < BB*CC) { g_Sp[tid] = 0.f; g_Sp2[tid] = 0.f; g_Sc[tid] = 0.f; g_Sc2[tid] = 0.f; }
    if (tid < CC*C2) {               // W2t[c*C2+o] = W2[o*CC+c]
        int c = tid / C2, o = tid % C2;
        g_W2t[tid] = W2[o*CC + c];
    }
    // 65536 threads cover C2*C2 exactly
    {
        int c = tid / C2, o = tid % C2;
        g_W3t[tid] = W3[o*C2 + c];
    }
}

// ---------------- K1: P = point@Wp^T ; Cc = center@Wc^T ----------------
__global__ void rn_pc(const float* __restrict__ pf, const float* __restrict__ cf,
                      const float* __restrict__ W1) {
    __shared__ float sr[CC];
    int r = blockIdx.x, o = threadIdx.x;              // 128 threads
    if (r < BNR) {
        sr[o] = pf[r*CC + o];
        __syncthreads();
        const float* w = W1 + o*(2*CC);               // Wp row o
        float acc = 0.f;
        #pragma unroll
        for (int c = 0; c < CC; c += 4) {
            float4 wv = *(const float4*)(w + c);
            acc = fmaf(wv.x, sr[c+0], acc);
            acc = fmaf(wv.y, sr[c+1], acc);
            acc = fmaf(wv.z, sr[c+2], acc);
            acc = fmaf(wv.w, sr[c+3], acc);
        }
        g_P[r*CC + o] = acc;
    } else {
        int rc = r - BNR;                             // 0..127
        sr[o] = cf[rc*CC + o];
        __syncthreads();
        const float* w = W1 + o*(2*CC) + CC;          // Wc row o
        float acc = 0.f;
        #pragma unroll
        for (int c = 0; c < CC; c += 4) {
            float4 wv = *(const float4*)(w + c);
            acc = fmaf(wv.x, sr[c+0], acc);
            acc = fmaf(wv.y, sr[c+1], acc);
            acc = fmaf(wv.z, sr[c+2], acc);
            acc = fmaf(wv.w, sr[c+3], acc);
        }
        g_Cc[rc*CC + o] = acc;
    }
}

// ---------------- K2a: partial sums for analytic bn1 stats ----------------
__global__ void rn_bn1a() {
    int b = blockIdx.x / 16, chunk = blockIdx.x % 16; // 32 blocks
    int o = threadIdx.x;                              // 128
    float sp = 0.f, sp2 = 0.f;
    int n0 = chunk * 128;
    for (int n = n0; n < n0 + 128; n++) {
        float v = g_P[(b*NN + n)*CC + o];
        sp += v; sp2 = fmaf(v, v, sp2);
    }
    atomicAdd(&g_Sp [b*CC + o], sp);
    atomicAdd(&g_Sp2[b*CC + o], sp2);
    if (chunk == 0) {
        float sc = 0.f, sc2 = 0.f;
        for (int m = 0; m < MM; m++) {
            float v = g_Cc[(b*MM + m)*CC + o];
            sc += v; sc2 = fmaf(v, v, sc2);
        }
        g_Sc [b*CC + o] = sc;
        g_Sc2[b*CC + o] = sc2;
    }
}

// ---------------- K2b: analytic bn1 affine ----------------
// z1[b,n,m,o] = P[b,n,o] + Cc[b,m,o]
// sum  = sum_b ( M*Sp[b] + N*Sc[b] )
// sumsq= sum_b ( M*Sp2[b] + 2*Sp[b]*Sc[b] + N*Sc2[b] )
__global__ void rn_bn1b(const float* __restrict__ g1, const float* __restrict__ b1) {
    int o = threadIdx.x;                              // 128
    float s = 0.f, q = 0.f;
    for (int b = 0; b < BB; b++) {
        float sp = g_Sp[b*CC+o], sp2 = g_Sp2[b*CC+o];
        float sc = g_Sc[b*CC+o], sc2 = g_Sc2[b*CC+o];
        s += (float)MM * sp + (float)NN * sc;
        q += (float)MM * sp2 + 2.f * sp * sc + (float)NN * sc2;
    }
    float inv = 1.f / (float)PCNT;
    float mean = s * inv;
    float var  = q * inv - mean * mean;
    float a = g1[o] * rsqrtf(var + EPS);
    g_a1[o] = a;
    g_d1[o] = b1[o] - mean * a;
}

// ---------------- K3: pass B — z2 = h1 @ W2^T (store + stats) ----------------
// smem: W2t[128][256] + CcT[128][64] + H1t[128][64] + Pr[128] + A1[128] + D1[128]
#define SMEM_B ((32768 + 8192 + 8192 + 128 + 128 + 128) * 4)
__global__ __launch_bounds__(256, 1) void rn_passB() {
    extern __shared__ float sm[];
    float* sW2t = sm;                // 32768  [k][o]
    float* sCcT = sW2t + 32768;      // 8192   [c][m]
    float* sH1t = sCcT + 8192;       // 8192   [c][m]
    float* sPr  = sH1t + 8192;       // 128
    float* sA1  = sPr  + 128;        // 128
    float* sD1  = sA1  + 128;        // 128

    int tid = threadIdx.x;
    for (int i = tid*4; i < CC*C2; i += 256*4)
        *(float4*)&sW2t[i] = *(const float4*)&g_W2t[i];
    if (tid < CC) { sA1[tid] = g_a1[tid]; sD1[tid] = g_d1[tid]; }

    int tx = tid & 31, wy = tid >> 5;
    int o0 = tx * 8, m0 = wy * 8;
    float tsum[8], tq[8];
    #pragma unroll
    for (int j = 0; j < 8; j++) { tsum[j] = 0.f; tq[j] = 0.f; }

    int curb = -1;
    for (int bn = blockIdx.x; bn < BNR; bn += gridDim.x) {
        int b = bn >> 11;
        __syncthreads();                               // prev GEMM done
        if (b != curb) {
            for (int e = tid; e < MM*CC; e += 256) {   // transpose Cc -> [c][m]
                int c = e & 127, m = e >> 7;
                sCcT[c*64 + m] = g_Cc[(b*MM + m)*CC + c];
            }
            curb = b;
        }
        if (tid < CC) sPr[tid] = g_P[bn*CC + tid];
        __syncthreads();
        for (int e = tid; e < MM*CC; e += 256) {       // h1 tile, transposed
            int m = e & 63, c = e >> 6;
            float v = fmaf(sA1[c], sPr[c] + sCcT[c*64 + m], sD1[c]);
            sH1t[c*64 + m] = (v >= 0.f) ? v : SLOPE * v;
        }
        __syncthreads();

        float acc[8][8];
        #pragma unroll
        for (int i = 0; i < 8; i++)
            #pragma unroll
            for (int j = 0; j < 8; j++) acc[i][j] = 0.f;

        #pragma unroll 2
        for (int k = 0; k < CC; k++) {
            float4 a0  = *(const float4*)&sH1t[(k << 6) + m0];
            float4 a1v = *(const float4*)&sH1t[(k << 6) + m0 + 4];
            float4 b0  = *(const float4*)&sW2t[(k << 8) + o0];
            float4 b1v = *(const float4*)&sW2t[(k << 8) + o0 + 4];
            float av[8] = {a0.x,a0.y,a0.z,a0.w,a1v.x,a1v.y,a1v.z,a1v.w};
            float bv[8] = {b0.x,b0.y,b0.z,b0.w,b1v.x,b1v.y,b1v.z,b1v.w};
            #pragma unroll
            for (int i = 0; i < 8; i++)
                #pragma unroll
                for (int j = 0; j < 8; j++)
                    acc[i][j] = fmaf(av[i], bv[j], acc[i][j]);
        }

        size_t base = (size_t)bn * (MM*C2);
        #pragma unroll
        for (int i = 0; i < 8; i++) {
            int m = m0 + i;
            float4 s0 = make_float4(acc[i][0], acc[i][1], acc[i][2], acc[i][3]);
            float4 s1 = make_float4(acc[i][4], acc[i][5], acc[i][6], acc[i][7]);
            *(float4*)&g_z2[base + m*C2 + o0]     = s0;
            *(float4*)&g_z2[base + m*C2 + o0 + 4] = s1;
        }
        #pragma unroll
        for (int j = 0; j < 8; j++) {
            float s = 0.f, q = 0.f;
            #pragma unroll
            for (int i = 0; i < 8; i++) { float v = acc[i][j]; s += v; q = fmaf(v, v, q); }
            tsum[j] += s; tq[j] += q;
        }
    }
    #pragma unroll
    for (int j = 0; j < 8; j++) {
        atomicAdd(&g_s2[o0 + j], tsum[j]);
        atomicAdd(&g_q2[o0 + j], tq[j]);
    }
}

// ---------------- K4: bn2 finalize ----------------
__global__ void rn_bn2fin(const float* __restrict__ g2, const float* __restrict__ b2) {
    int o = threadIdx.x;                              // 256
    float inv = 1.f / (float)PCNT;
    float mean = g_s2[o] * inv;
    float var  = g_q2[o] * inv - mean * mean;
    float a = g2[o] * rsqrtf(var + EPS);
    g_a2[o] = a; g_d2[o] = b2[o] - mean * a;
}

// ---------------- K5: pass C — z3 = h2 @ W3^T, max/min over m, stats ----------------
// smem: W3half[256][128] + H2t[256][68] + 4 reduce arrays [8][128]
#define SMEM_C ((32768 + 256*68 + 4*1024) * 4)
__global__ __launch_bounds__(256, 1) void rn_passC() {
    extern __shared__ float sm[];
    float* sW3  = sm;                 // 32768  [k][oo] (half of outputs)
    float* sH2t = sW3 + 32768;        // 256*68 [k][m] (pad 68 vs 64)
    float* rmax = sH2t + 256*68;      // 1024
    float* rmin = rmax + 1024;
    float* rsum = rmin + 1024;
    float* rsq  = rsum + 1024;

    int tid = threadIdx.x;
    float ra2 = g_a2[tid], rd2 = g_d2[tid];           // per-thread k-channel
    int tx = tid & 31, wy = tid >> 5;
    int o0 = tx * 4, m0 = wy * 8;

    int curh = -1;
    for (int w = blockIdx.x; w < 2*BNR; w += gridDim.x) {
        int h = w >> 12, bn = w & (BNR - 1);          // h-major: <=2 W3 loads/block
        __syncthreads();
        if (h != curh) {
            for (int e = tid; e < C2*128; e += 256) {
                int k = e >> 7, oo = e & 127;
                sW3[e] = g_W3t[k*C2 + h*128 + oo];
            }
            curh = h;
        }
        size_t base = (size_t)bn * (MM*C2);
        #pragma unroll 8
        for (int i = 0; i < MM; i++) {                // coalesced z2 read, bn2+lrelu
            float v = g_z2[base + i*C2 + tid];
            v = fmaf(ra2, v, rd2);
            v = (v >= 0.f) ? v : SLOPE * v;
            sH2t[tid*68 + i] = v;
        }
        __syncthreads();

        float acc[8][4];
        #pragma unroll
        for (int i = 0; i < 8; i++)
            #pragma unroll
            for (int j = 0; j < 4; j++) acc[i][j] = 0.f;

        #pragma unroll 2
        for (int k = 0; k < C2; k++) {
            float4 a0  = *(const float4*)&sH2t[k*68 + m0];
            float4 a1v = *(const float4*)&sH2t[k*68 + m0 + 4];
            float4 bv  = *(const float4*)&sW3[(k << 7) + o0];
            float av[8] = {a0.x,a0.y,a0.z,a0.w,a1v.x,a1v.y,a1v.z,a1v.w};
            float bb[4] = {bv.x,bv.y,bv.z,bv.w};
            #pragma unroll
            for (int i = 0; i < 8; i++)
                #pragma unroll
                for (int j = 0; j < 4; j++)
                    acc[i][j] = fmaf(av[i], bb[j], acc[i][j]);
        }

        #pragma unroll
        for (int j = 0; j < 4; j++) {
            float mx = -3.402823466e38f, mn = 3.402823466e38f, s = 0.f, q = 0.f;
            #pragma unroll
            for (int i = 0; i < 8; i++) {
                float v = acc[i][j];
                mx = fmaxf(mx, v); mn = fminf(mn, v);
                s += v; q = fmaf(v, v, q);
            }
            rmax[wy*128 + o0 + j] = mx;
            rmin[wy*128 + o0 + j] = mn;
            rsum[wy*128 + o0 + j] = s;
            rsq [wy*128 + o0 + j] = q;
        }
        __syncthreads();
        if (tid < 128) {
            float mx = -3.402823466e38f, mn = 3.402823466e38f, s = 0.f, q = 0.f;
            #pragma unroll
            for (int ww = 0; ww < 8; ww++) {
                mx = fmaxf(mx, rmax[ww*128 + tid]);
                mn = fminf(mn, rmin[ww*128 + tid]);
                s += rsum[ww*128 + tid];
                q += rsq [ww*128 + tid];
            }
            int ch = h*128 + tid;
            g_zmax[bn*C2 + ch] = mx;
            g_zmin[bn*C2 + ch] = mn;
            atomicAdd(&g_s3[ch], s);
            atomicAdd(&g_q3[ch], q);
        }
    }
}

// ---------------- K6: bn3 finalize ----------------
__global__ void rn_bn3fin(const float* __restrict__ g3, const float* __restrict__ b3) {
    int o = threadIdx.x;                              // 256
    float inv = 1.f / (float)PCNT;
    float mean = g_s3[o] * inv;
    float var  = g_q3[o] * inv - mean * mean;
    float a = g3[o] * rsqrtf(var + EPS);
    g_a3[o] = a; g_d3[o] = b3[o] - mean * a;
}

// ---------------- K7: h3 = lrelu(bn3(max_m z3)) ; z4 = h3@fc1^T + b ----------------
__global__ void rn_fc1(const float* __restrict__ fw, const float* __restrict__ fb) {
    __shared__ float sh[C2];
    int r = blockIdx.x, o = threadIdx.x;              // 128 threads
    for (int c = o; c < C2; c += 128) {
        float a3 = g_a3[c], d3 = g_d3[c];
        // max_m lrelu(bn3(z)) == lrelu(bn3(max z)) if a3>=0 else use min
        float z = (a3 >= 0.f) ? g_zmax[r*C2 + c] : g_zmin[r*C2 + c];
        float v = fmaf(a3, z, d3);
        sh[c] = (v >= 0.f) ? v : SLOPE * v;
    }
    __syncthreads();
    const float* wr = fw + o*C2;
    float acc = fb[o];
    #pragma unroll
    for (int c = 0; c < C2; c += 4) {
        float4 wv = *(const float4*)(wr + c);
        acc = fmaf(wv.x, sh[c+0], acc);
        acc = fmaf(wv.y, sh[c+1], acc);
        acc = fmaf(wv.z, sh[c+2], acc);
        acc = fmaf(wv.w, sh[c+3], acc);
    }
    g_z4[r*128 + o] = acc;
    atomicAdd(&g_s4[o], acc);
    atomicAdd(&g_q4[o], acc*acc);
}

// ---------------- K8: bn4 finalize (count = B*N = 4096) ----------------
__global__ void rn_bn4fin(const float* __restrict__ g4, const float* __restrict__ b4) {
    int o = threadIdx.x;                              // 128
    float inv = 1.f / (float)BNR;
    float mean = g_s4[o] * inv;
    float var  = g_q4[o] * inv - mean * mean;
    float a = g4[o] * rsqrtf(var + EPS);
    g_a4[o] = a; g_d4[o] = b4[o] - mean * a;
}

// ---------------- K9: h4 = relu(bn4(z4)) ; z5 = h4@fc2^T + b ----------------
__global__ void rn_fc2(const float* __restrict__ fw, const float* __restrict__ fb) {
    __shared__ float sh[128];
    int r = blockIdx.x, t = threadIdx.x;              // 128 threads
    float v = fmaf(g_a4[t], g_z4[r*128 + t], g_d4[t]);
    sh[t] = fmaxf(v, 0.f);
    __syncthreads();
    if (t < OUTC) {
        const float* wr = fw + t*128;
        float acc = fb[t];
        #pragma unroll
        for (int c = 0; c < 128; c += 4) {
            float4 wv = *(const float4*)(wr + c);
            acc = fmaf(wv.x, sh[c+0], acc);
            acc = fmaf(wv.y, sh[c+1], acc);
            acc = fmaf(wv.z, sh[c+2], acc);
            acc = fmaf(wv.w, sh[c+3], acc);
        }
        g_z5[r*OUTC + t] = acc;
        atomicAdd(&g_s5[t], acc);
        atomicAdd(&g_q5[t], acc*acc);
    }
}

// ---------------- K10: bn5 finalize (count = 4096) ----------------
__global__ void rn_bn5fin(const float* __restrict__ g5, const float* __restrict__ b5) {
    int o = threadIdx.x;                              // 64
    float inv = 1.f / (float)BNR;
    float mean = g_s5[o] * inv;
    float var  = g_q5[o] * inv - mean * mean;
    float a = g5[o] * rsqrtf(var + EPS);
    g_a5[o] = a; g_d5[o] = b5[o] - mean * a;
}

// ---------------- K11: out = relu(bn5(z5)) ----------------
__global__ void rn_out(float* __restrict__ out) {
    int i = blockIdx.x * 256 + threadIdx.x;           // covers 262144
    int o = i & (OUTC - 1);
    float v = fmaf(g_a5[o], g_z5[i], g_d5[o]);
    out[i] = fmaxf(v, 0.f);
}

// ---------------- launch ----------------
extern "C" void kernel_launch(void* const* d_in, const int* in_sizes, int n_in,
                              void* d_out, int out_size) {
    const float* pf   = (const float*)d_in[0];
    const float* cf   = (const float*)d_in[1];
    const float* W1   = (const float*)d_in[2];
    const float* g1   = (const float*)d_in[3];
    const float* b1   = (const float*)d_in[4];
    const float* W2   = (const float*)d_in[5];
    const float* g2   = (const float*)d_in[6];
    const float* b2   = (const float*)d_in[7];
    const float* W3   = (const float*)d_in[8];
    const float* g3   = (const float*)d_in[9];
    const float* b3   = (const float*)d_in[10];
    const float* fc1w = (const float*)d_in[11];
    const float* fc1b = (const float*)d_in[12];
    const float* g4   = (const float*)d_in[13];
    const float* b4   = (const float*)d_in[14];
    const float* fc2w = (const float*)d_in[15];
    const float* fc2b = (const float*)d_in[16];
    const float* g5   = (const float*)d_in[17];
    const float* b5   = (const float*)d_in[18];

    cudaFuncSetAttribute(rn_passB, cudaFuncAttributeMaxDynamicSharedMemorySize, SMEM_B);
    cudaFuncSetAttribute(rn_passC, cudaFuncAttributeMaxDynamicSharedMemorySize, SMEM_C);

    rn_prep  <<<256, 256>>>(W2, W3);
    rn_pc    <<<BNR + BB*MM, 128>>>(pf, cf, W1);
    rn_bn1a  <<<32, 128>>>();
    rn_bn1b  <<<1, 128>>>(g1, b1);
    rn_passB <<<148, 256, SMEM_B>>>();
    rn_bn2fin<<<1, 256>>>(g2, b2);
    rn_passC <<<148, 256, SMEM_C>>>();
    rn_bn3fin<<<1, 256>>>(g3, b3);
    rn_fc1   <<<BNR, 128>>>(fc1w, fc1b);
    rn_bn4fin<<<1, 128>>>(g4, b4);
    rn_fc2   <<<BNR, 128>>>(fc2w, fc2b);
    rn_bn5fin<<<1, 64>>>(g5, b5);
    rn_out   <<<PCNT/256, 256>>>((float*)d_out);   // 1024 blocks x 256 = 262144
}

// round 5
// speedup vs baseline: 2.2149x; 2.2149x over previous
#include <cuda_runtime.h>
#include <math.h>
#include <stdint.h>

// ---------------- problem constants ----------------
#define BB   2
#define NN   2048
#define MM   64
#define CC   128
#define C2   256
#define BNR  4096                 // BB*NN rows
#define PCNT 262144               // BNR*MM pairwise positions
#define OUTC 64
#define EPS  1e-5f
#define SLOPE 0.2f
#define NPAIR 2048                // BNR/2 : one tile = 2 bn rows = 128 M-rows

// ---------------- device scratch ----------------
__device__ float g_P  [BNR*CC];          // point @ Wp^T
__device__ float g_Cc [BB*MM*CC];        // center @ Wc^T   [b][m][c]
__device__ float g_CcT[BB*CC*MM];        // transposed      [b][c][m]
// z2 stored [bn][o][m] : index = bn*16384 + o*64 + m   (256MB fp32)
__device__ float g_z2 [(size_t)PCNT*C2];
__device__ float g_zmax[BNR*C2];
__device__ float g_zmin[BNR*C2];
__device__ float g_z4 [BNR*128];
__device__ float g_z5 [BNR*OUTC];

__device__ float g_Sp[BB*CC], g_Sp2[BB*CC], g_Sc[BB*CC], g_Sc2[BB*CC];
__device__ float g_a1[CC], g_d1[CC];
__device__ float g_s2[C2], g_q2[C2], g_a2[C2], g_d2[C2];
__device__ float g_s3[C2], g_q3[C2], g_a3[C2], g_d3[C2];
__device__ float g_s4[128], g_q4[128], g_a4[128], g_d4[128];
__device__ float g_s5[OUTC], g_q5[OUTC], g_a5[OUTC], g_d5[OUTC];

// ---------------- helpers ----------------
__device__ __forceinline__ float to_tf32(float x) {
    uint32_t u;
    asm("cvt.rna.tf32.f32 %0, %1;" : "=r"(u) : "f"(x));
    return __uint_as_float(u);
}
__device__ __forceinline__ void mma_tf32(float* c,
        uint32_t a0, uint32_t a1, uint32_t a2, uint32_t a3,
        uint32_t b0, uint32_t b1) {
    asm volatile(
        "mma.sync.aligned.m16n8k8.row.col.f32.tf32.tf32.f32 "
        "{%0,%1,%2,%3}, {%4,%5,%6,%7}, {%8,%9}, {%0,%1,%2,%3};"
        : "+f"(c[0]), "+f"(c[1]), "+f"(c[2]), "+f"(c[3])
        : "r"(a0), "r"(a1), "r"(a2), "r"(a3), "r"(b0), "r"(b1));
}
__device__ __forceinline__ float lrelu(float x) { return (x >= 0.f) ? x : SLOPE * x; }

// ---------------- K0: zero accumulators ----------------
__global__ void rn_prep() {
    int t = threadIdx.x;                              // 256
    g_s2[t] = 0.f; g_q2[t] = 0.f; g_s3[t] = 0.f; g_q3[t] = 0.f;
    g_Sp[t] = 0.f; g_Sp2[t] = 0.f; g_Sc[t] = 0.f; g_Sc2[t] = 0.f;
    if (t < 128) { g_s4[t] = 0.f; g_q4[t] = 0.f; }
    if (t < OUTC) { g_s5[t] = 0.f; g_q5[t] = 0.f; }
}

// ---------------- K1: P = point@Wp^T ; Cc = center@Wc^T ----------------
__global__ void rn_pc(const float* __restrict__ pf, const float* __restrict__ cf,
                      const float* __restrict__ W1) {
    __shared__ float sr[CC];
    int r = blockIdx.x, o = threadIdx.x;              // 128 threads
    if (r < BNR) {
        sr[o] = pf[r*CC + o];
        __syncthreads();
        const float* w = W1 + o*(2*CC);
        float acc = 0.f;
        #pragma unroll
        for (int c = 0; c < CC; c += 4) {
            float4 wv = *(const float4*)(w + c);
            acc = fmaf(wv.x, sr[c+0], acc); acc = fmaf(wv.y, sr[c+1], acc);
            acc = fmaf(wv.z, sr[c+2], acc); acc = fmaf(wv.w, sr[c+3], acc);
        }
        g_P[r*CC + o] = acc;
    } else {
        int rc = r - BNR;
        sr[o] = cf[rc*CC + o];
        __syncthreads();
        const float* w = W1 + o*(2*CC) + CC;
        float acc = 0.f;
        #pragma unroll
        for (int c = 0; c < CC; c += 4) {
            float4 wv = *(const float4*)(w + c);
            acc = fmaf(wv.x, sr[c+0], acc); acc = fmaf(wv.y, sr[c+1], acc);
            acc = fmaf(wv.z, sr[c+2], acc); acc = fmaf(wv.w, sr[c+3], acc);
        }
        g_Cc[rc*CC + o] = acc;
    }
}

// ---------------- K1b: transpose Cc -> [b][c][m] ----------------
__global__ void rn_cct() {
    int bc = blockIdx.x;                              // 256 : b*128 + c
    int m = threadIdx.x;                              // 64
    int b = bc >> 7, c = bc & 127;
    g_CcT[bc*64 + m] = g_Cc[(b*64 + m)*128 + c];
}

// ---------------- K2a/K2b: analytic bn1 ----------------
__global__ void rn_bn1a() {
    int b = blockIdx.x / 16, chunk = blockIdx.x % 16;
    int o = threadIdx.x;
    float sp = 0.f, sp2 = 0.f;
    int n0 = chunk * 128;
    for (int n = n0; n < n0 + 128; n++) {
        float v = g_P[(b*NN + n)*CC + o];
        sp += v; sp2 = fmaf(v, v, sp2);
    }
    atomicAdd(&g_Sp [b*CC + o], sp);
    atomicAdd(&g_Sp2[b*CC + o], sp2);
    if (chunk == 0) {
        float sc = 0.f, sc2 = 0.f;
        for (int m = 0; m < MM; m++) {
            float v = g_Cc[(b*MM + m)*CC + o];
            sc += v; sc2 = fmaf(v, v, sc2);
        }
        g_Sc [b*CC + o] = sc;
        g_Sc2[b*CC + o] = sc2;
    }
}
__global__ void rn_bn1b(const float* __restrict__ g1, const float* __restrict__ b1) {
    int o = threadIdx.x;
    float s = 0.f, q = 0.f;
    for (int b = 0; b < BB; b++) {
        float sp = g_Sp[b*CC+o], sp2 = g_Sp2[b*CC+o];
        float sc = g_Sc[b*CC+o], sc2 = g_Sc2[b*CC+o];
        s += (float)MM * sp + (float)NN * sc;
        q += (float)MM * sp2 + 2.f * sp * sc + (float)NN * sc2;
    }
    float inv = 1.f / (float)PCNT;
    float mean = s * inv;
    float var  = q * inv - mean * mean;
    float a = g1[o] * rsqrtf(var + EPS);
    g_a1[o] = a;
    g_d1[o] = b1[o] - mean * a;
}

// =====================================================================
// K3: passB (mma.sync tf32) : z2 = h1 @ W2^T, store [bn][o][m], bn2 stats
// smem floats: W2 [256][132]=33792 | A [128][136]=17408 | stage [32][132]=4224
//              s2acc 256 | q2acc 256        total 55936 floats = 223744 B
// =====================================================================
#define PB_PW 132
#define PB_PA 136
#define PB_PS 132
#define SMEM_PB (55936*4)
__global__ __launch_bounds__(256, 1) void rn_passB_mma(const float* __restrict__ W2) {
    extern __shared__ float sm[];
    float* sW2   = sm;                 // [o][k] pitch 132
    float* sA    = sW2 + 256*PB_PW;    // [k][m] pitch 136
    float* stage = sA + 128*PB_PA;     // [o_l][m'] pitch 132
    float* s2a   = stage + 32*PB_PS;   // 256
    float* q2a   = s2a + 256;          // 256
    __shared__ float sa1[128], sd1[128];

    int tid = threadIdx.x, wid = tid >> 5, lane = tid & 31;
    int g = lane >> 2, t = lane & 3;
    int wm = wid >> 2, wn = wid & 3;   // warp tile 64(M) x 64(N)

    if (tid < 128) { sa1[tid] = g_a1[tid]; sd1[tid] = g_d1[tid]; }
    if (tid < 256) { s2a[tid] = 0.f; q2a[tid] = 0.f; }
    // W2 [o=256][k=128] -> sW2 (tf32-rounded)
    {
        const float4* wp = (const float4*)(W2 + tid*128);
        float* dst = sW2 + tid*PB_PW;
        #pragma unroll
        for (int u = 0; u < 32; u++) {
            float4 v = wp[u];
            dst[4*u+0] = to_tf32(v.x); dst[4*u+1] = to_tf32(v.y);
            dst[4*u+2] = to_tf32(v.z); dst[4*u+3] = to_tf32(v.w);
        }
    }
    __syncthreads();

    int s_q = tid & 15;                 // m-quad id for A build
    int c_hi = tid >> 4;                // 0..15

    for (int pair = blockIdx.x; pair < NPAIR; pair += gridDim.x) {
        int b = pair >> 10;
        // ---- build A = h1 [k=c][m'] (tf32), m' = bnl*64 + m ----
        #pragma unroll
        for (int i = 0; i < 8; i++) {
            int c = c_hi + 16*i;
            float a1v = sa1[c], d1v = sd1[c];
            float4 cv = *(const float4*)(g_CcT + (b*128 + c)*64 + 4*s_q);
            #pragma unroll
            for (int j = 0; j < 2; j++) {
                float pv = g_P[(pair*2 + j)*128 + c];
                float4 h;
                h.x = to_tf32(lrelu(fmaf(a1v, pv + cv.x, d1v)));
                h.y = to_tf32(lrelu(fmaf(a1v, pv + cv.y, d1v)));
                h.z = to_tf32(lrelu(fmaf(a1v, pv + cv.z, d1v)));
                h.w = to_tf32(lrelu(fmaf(a1v, pv + cv.w, d1v)));
                *(float4*)(sA + c*PB_PA + 4*s_q + 64*j) = h;
            }
        }
        __syncthreads();

        // ---- MMA: 64x64 per warp, K=128 ----
        float acc[4][8][4];
        #pragma unroll
        for (int mt = 0; mt < 4; mt++)
            #pragma unroll
            for (int nt = 0; nt < 8; nt++)
                #pragma unroll
                for (int e = 0; e < 4; e++) acc[mt][nt][e] = 0.f;

        #pragma unroll 4
        for (int ks = 0; ks < 16; ks++) {
            int k0 = ks * 8;
            uint32_t af[4][4];
            #pragma unroll
            for (int mt = 0; mt < 4; mt++) {
                const float* ap = sA + (k0 + t)*PB_PA + wm*64 + mt*16 + g;
                af[mt][0] = __float_as_uint(ap[0]);
                af[mt][1] = __float_as_uint(ap[8]);
                af[mt][2] = __float_as_uint(ap[4*PB_PA]);
                af[mt][3] = __float_as_uint(ap[4*PB_PA + 8]);
            }
            #pragma unroll
            for (int nt = 0; nt < 8; nt++) {
                const float* bp = sW2 + (wn*64 + nt*8 + g)*PB_PW + k0 + t;
                uint32_t b0 = __float_as_uint(bp[0]);
                uint32_t b1 = __float_as_uint(bp[4]);
                #pragma unroll
                for (int mt = 0; mt < 4; mt++)
                    mma_tf32(acc[mt][nt], af[mt][0], af[mt][1], af[mt][2], af[mt][3], b0, b1);
            }
        }
        __syncthreads();   // A consumed

        // ---- epilogue: 8 chunks of 32 o-cols via smem stage ----
        #pragma unroll
        for (int ch = 0; ch < 8; ch++) {
            if ((ch >> 1) == wn) {
                #pragma unroll
                for (int ntl = 0; ntl < 4; ntl++) {
                    int nt = (ch & 1)*4 + ntl;
                    int ol = ntl*8 + 2*t;
                    #pragma unroll
                    for (int mt = 0; mt < 4; mt++) {
                        int row = wm*64 + mt*16 + g;
                        stage[ ol   *PB_PS + row    ] = acc[mt][nt][0];
                        stage[(ol+1)*PB_PS + row    ] = acc[mt][nt][1];
                        stage[ ol   *PB_PS + row + 8] = acc[mt][nt][2];
                        stage[(ol+1)*PB_PS + row + 8] = acc[mt][nt][3];
                    }
                }
            }
            __syncthreads();
            // coalesced write: warp w handles rows (p*8 + w)
            #pragma unroll
            for (int p = 0; p < 4; p++) {
                int rl = p*8 + wid;
                int o = ch*32 + rl;
                float4 v = *(float4*)(stage + rl*PB_PS + lane*4);
                float s = v.x + v.y + v.z + v.w;
                float q = fmaf(v.x, v.x, fmaf(v.y, v.y, fmaf(v.z, v.z, v.w*v.w)));
                #pragma unroll
                for (int mk = 16; mk >= 1; mk >>= 1) {
                    s += __shfl_xor_sync(0xFFFFFFFFu, s, mk);
                    q += __shfl_xor_sync(0xFFFFFFFFu, q, mk);
                }
                if (lane == 0) { atomicAdd(&s2a[o], s); atomicAdd(&q2a[o], q); }
                int bnl = lane >> 4, m = (lane*4) & 63;
                *(float4*)&g_z2[(size_t)(pair*2 + bnl)*16384 + (size_t)o*64 + m] = v;
            }
            __syncthreads();
        }
    }
    __syncthreads();
    atomicAdd(&g_s2[tid], s2a[tid]);
    atomicAdd(&g_q2[tid], q2a[tid]);
}

// ---------------- K4: bn2 finalize ----------------
__global__ void rn_bn2fin(const float* __restrict__ g2, const float* __restrict__ b2) {
    int o = threadIdx.x;
    float inv = 1.f / (float)PCNT;
    float mean = g_s2[o] * inv;
    float var  = g_q2[o] * inv - mean * mean;
    float a = g2[o] * rsqrtf(var + EPS);
    g_a2[o] = a; g_d2[o] = b2[o] - mean * a;
}

// =====================================================================
// K5: passC (mma.sync tf32) : z3 = h2 @ W3^T (N half h), max/min + stats
// smem floats: W3 [128][260]=33280 | A [128][136]=17408 | s3a 256 | q3a 256
//              total 51200 floats = 204800 B
// =====================================================================
#define PC_PW 260
#define PC_PA 136
#define SMEM_PC (51200*4)
__global__ __launch_bounds__(256, 1) void rn_passC_mma(const float* __restrict__ W3) {
    extern __shared__ float sm[];
    float* sW3 = sm;                 // [o][k] pitch 260 (K=256)
    float* sA  = sW3 + 128*PC_PW;    // [k][m'] pitch 136 (k-chunk of 128)
    float* s3a = sA + 128*PC_PA;     // 256
    float* q3a = s3a + 256;          // 256
    __shared__ float sa2[256], sd2[256];

    int tid = threadIdx.x, wid = tid >> 5, lane = tid & 31;
    int g = lane >> 2, t = lane & 3;
    int wm = wid >> 2, wn = wid & 3;  // warp tile 64(M) x 32(N)

    sa2[tid] = g_a2[tid]; sd2[tid] = g_d2[tid];
    s3a[tid] = 0.f; q3a[tid] = 0.f;
    __syncthreads();

    int curh = -1;
    for (int w = blockIdx.x; w < 2*NPAIR; w += gridDim.x) {
        int h = w >> 11, pair = w & (NPAIR - 1);     // h-major
        if (h != curh) {
            __syncthreads();
            // W3 half [o=128][k=256] -> sW3 (tf32)
            int o = tid >> 1, kh = (tid & 1) * 128;
            const float4* wp = (const float4*)(W3 + (size_t)(h*128 + o)*256 + kh);
            float* dst = sW3 + o*PC_PW + kh;
            #pragma unroll
            for (int u = 0; u < 32; u++) {
                float4 v = wp[u];
                dst[4*u+0] = to_tf32(v.x); dst[4*u+1] = to_tf32(v.y);
                dst[4*u+2] = to_tf32(v.z); dst[4*u+3] = to_tf32(v.w);
            }
            FENCE: ;
            __syncthreads();
            curh = h;
        }

        float acc[4][4][4];
        #pragma unroll
        for (int mt = 0; mt < 4; mt++)
            #pragma unroll
            for (int nt = 0; nt < 4; nt++)
                #pragma unroll
                for (int e = 0; e < 4; e++) acc[mt][nt][e] = 0.f;

        #pragma unroll
        for (int kc = 0; kc < 2; kc++) {
            // ---- build A chunk: z2 -> bn2 + lrelu -> tf32, [k][m'] ----
            int bnl = lane >> 4, m = (lane*4) & 63;
            #pragma unroll
            for (int i = 0; i < 16; i++) {
                int kl = wid + i*8;
                int kg = kc*128 + kl;
                float a2v = sa2[kg], d2v = sd2[kg];
                float4 v = *(const float4*)&g_z2[(size_t)(pair*2 + bnl)*16384 + (size_t)kg*64 + m];
                float4 hx;
                hx.x = to_tf32(lrelu(fmaf(a2v, v.x, d2v)));
                hx.y = to_tf32(lrelu(fmaf(a2v, v.y, d2v)));
                hx.z = to_tf32(lrelu(fmaf(a2v, v.z, d2v)));
                hx.w = to_tf32(lrelu(fmaf(a2v, v.w, d2v)));
                *(float4*)(sA + kl*PC_PA + lane*4) = hx;
            }
            __syncthreads();
            // ---- MMA: 16 k-steps ----
            #pragma unroll 4
            for (int ks = 0; ks < 16; ks++) {
                int k0 = ks * 8;
                uint32_t af[4][4];
                #pragma unroll
                for (int mt = 0; mt < 4; mt++) {
                    const float* ap = sA + (k0 + t)*PC_PA + wm*64 + mt*16 + g;
                    af[mt][0] = __float_as_uint(ap[0]);
                    af[mt][1] = __float_as_uint(ap[8]);
                    af[mt][2] = __float_as_uint(ap[4*PC_PA]);
                    af[mt][3] = __float_as_uint(ap[4*PC_PA + 8]);
                }
                #pragma unroll
                for (int nt = 0; nt < 4; nt++) {
                    const float* bp = sW3 + (wn*32 + nt*8 + g)*PC_PW + kc*128 + k0 + t;
                    uint32_t b0 = __float_as_uint(bp[0]);
                    uint32_t b1 = __float_as_uint(bp[4]);
                    #pragma unroll
                    for (int mt = 0; mt < 4; mt++)
                        mma_tf32(acc[mt][nt], af[mt][0], af[mt][1], af[mt][2], af[mt][3], b0, b1);
                }
            }
            __syncthreads();   // A consumed before next chunk overwrites
        }

        // ---- reduce over m from fragments: warp wm <-> bn = pair*2+wm ----
        #pragma unroll
        for (int nt = 0; nt < 4; nt++) {
            #pragma unroll
            for (int e = 0; e < 2; e++) {
                float mx = -3.402823466e38f, mn = 3.402823466e38f, s = 0.f, q = 0.f;
                #pragma unroll
                for (int mt = 0; mt < 4; mt++) {
                    float v0 = acc[mt][nt][e], v1 = acc[mt][nt][e+2];
                    mx = fmaxf(mx, fmaxf(v0, v1));
                    mn = fminf(mn, fminf(v0, v1));
                    s += v0 + v1;
                    q = fmaf(v0, v0, q); q = fmaf(v1, v1, q);
                }
                #pragma unroll
                for (int mk = 4; mk <= 16; mk <<= 1) {
                    mx = fmaxf(mx, __shfl_xor_sync(0xFFFFFFFFu, mx, mk));
                    mn = fminf(mn, __shfl_xor_sync(0xFFFFFFFFu, mn, mk));
                    s += __shfl_xor_sync(0xFFFFFFFFu, s, mk);
                    q += __shfl_xor_sync(0xFFFFFFFFu, q, mk);
                }
                if (lane < 4) {
                    int gc = h*128 + wn*32 + nt*8 + 2*lane + e;
                    int bn = pair*2 + wm;
                    g_zmax[bn*C2 + gc] = mx;
                    g_zmin[bn*C2 + gc] = mn;
                    atomicAdd(&s3a[gc], s);
                    atomicAdd(&q3a[gc], q);
                }
            }
        }
    }
    __syncthreads();
    atomicAdd(&g_s3[tid], s3a[tid]);
    atomicAdd(&g_q3[tid], q3a[tid]);
}

// ---------------- K6: bn3 finalize ----------------
__global__ void rn_bn3fin(const float* __restrict__ g3, const float* __restrict__ b3) {
    int o = threadIdx.x;
    float inv = 1.f / (float)PCNT;
    float mean = g_s3[o] * inv;
    float var  = g_q3[o] * inv - mean * mean;
    float a = g3[o] * rsqrtf(var + EPS);
    g_a3[o] = a; g_d3[o] = b3[o] - mean * a;
}

// ---------------- K7: fc1 ----------------
__global__ void rn_fc1(const float* __restrict__ fw, const float* __restrict__ fb) {
    __shared__ float sh[C2];
    int r = blockIdx.x, o = threadIdx.x;              // 128 threads
    for (int c = o; c < C2; c += 128) {
        float a3 = g_a3[c], d3 = g_d3[c];
        float z = (a3 >= 0.f) ? g_zmax[r*C2 + c] : g_zmin[r*C2 + c];
        float v = fmaf(a3, z, d3);
        sh[c] = (v >= 0.f) ? v : SLOPE * v;
    }
    __syncthreads();
    const float* wr = fw + o*C2;
    float acc = fb[o];
    #pragma unroll
    for (int c = 0; c < C2; c += 4) {
        float4 wv = *(const float4*)(wr + c);
        acc = fmaf(wv.x, sh[c+0], acc); acc = fmaf(wv.y, sh[c+1], acc);
        acc = fmaf(wv.z, sh[c+2], acc); acc = fmaf(wv.w, sh[c+3], acc);
    }
    g_z4[r*128 + o] = acc;
    atomicAdd(&g_s4[o], acc);
    atomicAdd(&g_q4[o], acc*acc);
}
__global__ void rn_bn4fin(const float* __restrict__ g4, const float* __restrict__ b4) {
    int o = threadIdx.x;
    float inv = 1.f / (float)BNR;
    float mean = g_s4[o] * inv;
    float var  = g_q4[o] * inv - mean * mean;
    float a = g4[o] * rsqrtf(var + EPS);
    g_a4[o] = a; g_d4[o] = b4[o] - mean * a;
}

// ---------------- K9: fc2 ----------------
__global__ void rn_fc2(const float* __restrict__ fw, const float* __restrict__ fb) {
    __shared__ float sh[128];
    int r = blockIdx.x, t = threadIdx.x;
    float v = fmaf(g_a4[t], g_z4[r*128 + t], g_d4[t]);
    sh[t] = fmaxf(v, 0.f);
    __syncthreads();
    if (t < OUTC) {
        const float* wr = fw + t*128;
        float acc = fb[t];
        #pragma unroll
        for (int c = 0; c < 128; c += 4) {
            float4 wv = *(const float4*)(wr + c);
            acc = fmaf(wv.x, sh[c+0], acc); acc = fmaf(wv.y, sh[c+1], acc);
            acc = fmaf(wv.z, sh[c+2], acc); acc = fmaf(wv.w, sh[c+3], acc);
        }
        g_z5[r*OUTC + t] = acc;
        atomicAdd(&g_s5[t], acc);
        atomicAdd(&g_q5[t], acc*acc);
    }
}
__global__ void rn_bn5fin(const float* __restrict__ g5, const float* __restrict__ b5) {
    int o = threadIdx.x;
    float inv = 1.f / (float)BNR;
    float mean = g_s5[o] * inv;
    float var  = g_q5[o] * inv - mean * mean;
    float a = g5[o] * rsqrtf(var + EPS);
    g_a5[o] = a; g_d5[o] = b5[o] - mean * a;
}

// ---------------- K11: output ----------------
__global__ void rn_out(float* __restrict__ out) {
    int i = blockIdx.x * 256 + threadIdx.x;           // 262144 total
    int o = i & (OUTC - 1);
    float v = fmaf(g_a5[o], g_z5[i], g_d5[o]);
    out[i] = fmaxf(v, 0.f);
}

// ---------------- launch ----------------
extern "C" void kernel_launch(void* const* d_in, const int* in_sizes, int n_in,
                              void* d_out, int out_size) {
    const float* pf   = (const float*)d_in[0];
    const float* cf   = (const float*)d_in[1];
    const float* W1   = (const float*)d_in[2];
    const float* g1   = (const float*)d_in[3];
    const float* b1   = (const float*)d_in[4];
    const float* W2   = (const float*)d_in[5];
    const float* g2   = (const float*)d_in[6];
    const float* b2   = (const float*)d_in[7];
    const float* W3   = (const float*)d_in[8];
    const float* g3   = (const float*)d_in[9];
    const float* b3   = (const float*)d_in[10];
    const float* fc1w = (const float*)d_in[11];
    const float* fc1b = (const float*)d_in[12];
    const float* g4   = (const float*)d_in[13];
    const float* b4   = (const float*)d_in[14];
    const float* fc2w = (const float*)d_in[15];
    const float* fc2b = (const float*)d_in[16];
    const float* g5   = (const float*)d_in[17];
    const float* b5   = (const float*)d_in[18];

    cudaFuncSetAttribute(rn_passB_mma, cudaFuncAttributeMaxDynamicSharedMemorySize, SMEM_PB);
    cudaFuncSetAttribute(rn_passC_mma, cudaFuncAttributeMaxDynamicSharedMemorySize, SMEM_PC);

    rn_prep  <<<1, 256>>>();
    rn_pc    <<<BNR + BB*MM, 128>>>(pf, cf, W1);
    rn_cct   <<<256, 64>>>();
    rn_bn1a  <<<32, 128>>>();
    rn_bn1b  <<<1, 128>>>(g1, b1);
    rn_passB_mma <<<148, 256, SMEM_PB>>>(W2);
    rn_bn2fin<<<1, 256>>>(g2, b2);
    rn_passC_mma <<<148, 256, SMEM_PC>>>(W3);
    rn_bn3fin<<<1, 256>>>(g3, b3);
    rn_fc1   <<<BNR, 128>>>(fc1w, fc1b);
    rn_bn4fin<<<1, 128>>>(g4, b4);
    rn_fc2   <<<BNR, 128>>>(fc2w, fc2b);
    rn_bn5fin<<<1, 64>>>(g5, b5);
    rn_out   <<<PCNT/256, 256>>>((float*)d_out);
}